// round 10
// baseline (speedup 1.0000x reference)
#include <cuda_runtime.h>
#include <cstdint>

#define NB 4
#define NN 4096
#define FIN 256
#define FOUT 128
#define ROWS (NB*NN)
#define NCH 128            // 4096/32 k-chunks
#define PSTR 40            // smem row stride (words); 40 mod 32 = 8 -> conflict-free LDS.64

// -------- scratch (static __device__, no allocs) --------
__device__ float    g_Wh[(size_t)ROWS*FOUT];            // 8 MB   Wh row-major [row][f]
__device__ float    g_WhB[(size_t)NB*FOUT*NN];          // 8 MB   [b][f][k-pos] tf32 (pi-ordered, pair-permuted)
__device__ float    g_Wh1[ROWS];
__device__ float    g_Wh2[ROWS];
__device__ float    g_Wh2p[NB*NN];                      // Wh2 in pi order
__device__ float    g_invZ[ROWS];
__device__ unsigned g_maskT[(size_t)NB*NCH*NN];         // 8 MB   [b][chunk][n], bit l <-> m = pi(chunk,l)

// pi(c, l) = (c>>2)*128 + 4*l + (c&3)

__device__ __forceinline__ float to_tf32(float x) {
    uint32_t b; asm("cvt.rna.tf32.f32 %0, %1;" : "=r"(b) : "f"(x));
    return __uint_as_float(b);
}
__device__ __forceinline__ void mma_tf32(float* d, uint32_t a0, uint32_t a1, uint32_t a2, uint32_t a3,
                                         uint32_t b0, uint32_t b1) {
    asm volatile("mma.sync.aligned.m16n8k8.row.col.f32.tf32.tf32.f32 "
                 "{%0,%1,%2,%3}, {%4,%5,%6,%7}, {%8,%9}, {%0,%1,%2,%3};"
                 : "+f"(d[0]), "+f"(d[1]), "+f"(d[2]), "+f"(d[3])
                 : "r"(a0), "r"(a1), "r"(a2), "r"(a3), "r"(b0), "r"(b1));
}
__device__ __forceinline__ uint32_t smem_u32(const void* p) {
    uint32_t a;
    asm("{ .reg .u64 t; cvta.to.shared.u64 t, %1; cvt.u32.u64 %0, t; }" : "=r"(a) : "l"(p));
    return a;
}
__device__ __forceinline__ void cp_async16(uint32_t dst, const void* src) {
    asm volatile("cp.async.ca.shared.global [%0], [%1], 16;" :: "r"(dst), "l"(src));
}
#define CP_COMMIT() asm volatile("cp.async.commit_group;" ::: "memory")
#define CP_WAIT1()  asm volatile("cp.async.wait_group 1;" ::: "memory")

// ====== Kernel 1: Wh = h @ W  (fp32 tiled GEMM) + fused Wh1/Wh2 rowvec ======
__global__ void __launch_bounds__(256) k_gemm(const float* __restrict__ h,
                                              const float* __restrict__ W,
                                              const float* __restrict__ a) {
    __shared__ float As[64][32];
    __shared__ float Bsm[32][FOUT];
    const int block_row = blockIdx.x * 64;
    const int tid = threadIdx.x;
    const int tx = tid & 31, ty = tid >> 5;
    const float4 a1v = ((const float4*)a)[tx];
    const float4 a2v = ((const float4*)a)[32 + tx];
    float acc[8][4];
#pragma unroll
    for (int r = 0; r < 8; r++) { acc[r][0]=acc[r][1]=acc[r][2]=acc[r][3]=0.f; }
    for (int k0 = 0; k0 < FIN; k0 += 32) {
#pragma unroll
        for (int i = tid; i < 64*32; i += 256) {
            int r = i >> 5, c = i & 31;
            As[r][c] = h[(size_t)(block_row + r)*FIN + k0 + c];
        }
#pragma unroll
        for (int i = tid; i < 32*FOUT; i += 256) {
            int r = i >> 7, c = i & 127;
            Bsm[r][c] = W[(size_t)(k0 + r)*FOUT + c];
        }
        __syncthreads();
#pragma unroll
        for (int kk = 0; kk < 32; kk++) {
            float4 bv = *(const float4*)&Bsm[kk][tx*4];
#pragma unroll
            for (int r = 0; r < 8; r++) {
                float av = As[ty*8 + r][kk];
                acc[r][0] += av*bv.x; acc[r][1] += av*bv.y;
                acc[r][2] += av*bv.z; acc[r][3] += av*bv.w;
            }
        }
        __syncthreads();
    }
#pragma unroll
    for (int r = 0; r < 8; r++) {
        *(float4*)&g_Wh[(size_t)(block_row + ty*8 + r)*FOUT + tx*4] =
            make_float4(acc[r][0], acc[r][1], acc[r][2], acc[r][3]);
        // fused rowvec: Wh1/Wh2 for this row (reduce over lanes = F dim)
        float s1 = acc[r][0]*a1v.x + acc[r][1]*a1v.y + acc[r][2]*a1v.z + acc[r][3]*a1v.w;
        float s2 = acc[r][0]*a2v.x + acc[r][1]*a2v.y + acc[r][2]*a2v.z + acc[r][3]*a2v.w;
#pragma unroll
        for (int off = 16; off; off >>= 1) {
            s1 += __shfl_xor_sync(0xffffffffu, s1, off);
            s2 += __shfl_xor_sync(0xffffffffu, s2, off);
        }
        if (tx == 0) {
            g_Wh1[block_row + ty*8 + r] = s1;
            g_Wh2[block_row + ty*8 + r] = s2;
        }
    }
}

// ==== Kernel 2: gather Wh rows in pi order -> WhB [b][f][k], pair-permuted; also Wh2p ====
__global__ void __launch_bounds__(128) k_trans() {
    __shared__ float ts[32*128];   // [l][f]
    const int cp = blockIdx.x, b = blockIdx.y, tid = threadIdx.x;
    const int mbase = (cp >> 2) << 7, moff = cp & 3;
#pragma unroll
    for (int i = 0; i < 8; i++) {
        int idx = tid + 128*i;          // float4 index, 1024 total
        int l = idx >> 5, f4 = idx & 31;
        int m = mbase + 4*l + moff;
        ((float4*)ts)[idx] = *(((const float4*)(g_Wh + (size_t)(b*NN + m)*FOUT)) + f4);
    }
    if (tid < 32)
        g_Wh2p[b*NN + cp*32 + tid] = g_Wh2[b*NN + mbase + 4*tid + moff];
    __syncthreads();
    const int f = tid;
    float* dst = g_WhB + ((size_t)b*FOUT + f)*NN + cp*32;
#pragma unroll
    for (int s = 0; s < 4; s++)
#pragma unroll
        for (int t = 0; t < 4; t++) {
            float2 v;
            v.x = to_tf32(ts[(s*8 + t    )*128 + f]);
            v.y = to_tf32(ts[(s*8 + t + 4)*128 + f]);
            *(float2*)(dst + s*8 + 2*t) = v;
        }
}

// ==== Kernel 3: one pass over adj (2x int4/iter): pack pi mask + softmax denom ====
__global__ void __launch_bounds__(256) k_stats(const int* __restrict__ adj) {
    int warp = (blockIdx.x * blockDim.x + threadIdx.x) >> 5;
    int lane = threadIdx.x & 31;
    if (warp >= ROWS) return;
    const int row = warp, b = row >> 12, n = row & (NN-1);
    const float w1 = g_Wh1[row];
    const int4*   arow = (const int4*)(adj + (size_t)row * NN);
    const float4* w2   = (const float4*)(g_Wh2 + (size_t)b * NN);
    unsigned* mbase = g_maskT + (size_t)b*NCH*NN + n;
    float sum = 0.f;
#pragma unroll 2
    for (int gg = 0; gg < 16; gg++) {
        int4   av0 = arow[gg*64 + lane];
        int4   av1 = arow[gg*64 + 32 + lane];
        float4 ev0 = w2[gg*64 + lane];
        float4 ev1 = w2[gg*64 + 32 + lane];
        // --- half 0 ---
        {
            float e0 = w1 + ev0.x; e0 = (e0>=0.f)?e0:0.2f*e0;
            float e1 = w1 + ev0.y; e1 = (e1>=0.f)?e1:0.2f*e1;
            float e2 = w1 + ev0.z; e2 = (e2>=0.f)?e2:0.2f*e2;
            float e3 = w1 + ev0.w; e3 = (e3>=0.f)?e3:0.2f*e3;
            unsigned b0 = __ballot_sync(0xffffffffu, av0.x > 0);
            unsigned b1 = __ballot_sync(0xffffffffu, av0.y > 0);
            unsigned b2 = __ballot_sync(0xffffffffu, av0.z > 0);
            unsigned b3 = __ballot_sync(0xffffffffu, av0.w > 0);
            if (av0.x > 0) sum += __expf(e0);
            if (av0.y > 0) sum += __expf(e1);
            if (av0.z > 0) sum += __expf(e2);
            if (av0.w > 0) sum += __expf(e3);
            if (lane < 4) {
                unsigned bb = (lane == 0) ? b0 : (lane == 1) ? b1 : (lane == 2) ? b2 : b3;
                mbase[(size_t)(gg*8 + lane) * NN] = bb;
            }
        }
        // --- half 1 ---
        {
            float e0 = w1 + ev1.x; e0 = (e0>=0.f)?e0:0.2f*e0;
            float e1 = w1 + ev1.y; e1 = (e1>=0.f)?e1:0.2f*e1;
            float e2 = w1 + ev1.z; e2 = (e2>=0.f)?e2:0.2f*e2;
            float e3 = w1 + ev1.w; e3 = (e3>=0.f)?e3:0.2f*e3;
            unsigned b0 = __ballot_sync(0xffffffffu, av1.x > 0);
            unsigned b1 = __ballot_sync(0xffffffffu, av1.y > 0);
            unsigned b2 = __ballot_sync(0xffffffffu, av1.z > 0);
            unsigned b3 = __ballot_sync(0xffffffffu, av1.w > 0);
            if (av1.x > 0) sum += __expf(e0);
            if (av1.y > 0) sum += __expf(e1);
            if (av1.z > 0) sum += __expf(e2);
            if (av1.w > 0) sum += __expf(e3);
            if (lane < 4) {
                unsigned bb = (lane == 0) ? b0 : (lane == 1) ? b1 : (lane == 2) ? b2 : b3;
                mbase[(size_t)(gg*8 + 4 + lane) * NN] = bb;
            }
        }
    }
#pragma unroll
    for (int off = 16; off; off >>= 1) sum += __shfl_xor_sync(0xffffffffu, sum, off);
    if (lane == 0) g_invZ[row] = 1.f / sum;
}

// ============ Kernel 4: h' = attn @ Wh via mma.sync tf32, pipelined ============
// 256 threads (8 warps: 2M x 4N, warp tile 32x32). M tile 64 -> 2 CTAs/SM.
// cp.async 3-stage W ring, 2-stage P ring, ONE __syncthreads per chunk.
__global__ void __launch_bounds__(256, 2) k_pv(float* __restrict__ out) {
    __shared__ float Ws[3][128*PSTR];   // 60 KB  Wh^T tiles
    __shared__ float Ps[2][64*PSTR];    // 20 KB  P tiles

    const int b   = blockIdx.y;
    const int n0  = blockIdx.x * 64;
    const int tid = threadIdx.x;
    const int warp = tid >> 5, lane = tid & 31;
    const int g = lane >> 2, t = lane & 3;
    const int mband = (warp >> 2) * 32;      // 2 M bands
    const int nband = (warp & 3) * 32;       // 4 N bands

    // P-producer role: row + one 8-kpos group
    const int mrow = tid >> 2;               // 0..63
    const int kq   = (tid & 3) * 8;
    const float w1 = g_Wh1[b*NN + n0 + mrow];
    const float iz = g_invZ[b*NN + n0 + mrow];
    const unsigned* maskrow = g_maskT + (size_t)b*NCH*NN + n0 + mrow;
    const float*    wh2p    = g_Wh2p + b*NN + kq;

    // W copy role: 4 x 16B lines per thread per chunk (f row = tid>>1)
    const int wf  = tid >> 1;
    const int wp  = (tid & 1) * 16;
    const float* gWb = g_WhB + (size_t)b*FOUT*NN;
    const uint32_t wsBase = smem_u32(&Ws[0][0]);

    float acc[2][4][4];
#pragma unroll
    for (int mf = 0; mf < 2; mf++)
#pragma unroll
        for (int nf = 0; nf < 4; nf++)
#pragma unroll
            for (int i = 0; i < 4; i++) acc[mf][nf][i] = 0.f;

    // ---- prologue: issue W0, W1 ----
#pragma unroll
    for (int c = 0; c < 2; c++) {
        uint32_t ds = wsBase + (uint32_t)(c)*(128*PSTR*4);
        const float* gs = gWb + (size_t)wf*NN + c*32 + wp;
#pragma unroll
        for (int i = 0; i < 4; i++)
            cp_async16(ds + (wf*PSTR + wp + 4*i)*4, gs + 4*i);
        CP_COMMIT();
    }
    // P inputs for c=0, prefetch c=1
    unsigned mw   = maskrow[0];
    float4 w2a    = *(const float4*)(wh2p + 0);
    float4 w2b    = *(const float4*)(wh2p + 4);
    unsigned mw_n = maskrow[NN];
    float4 w2a_n  = *(const float4*)(wh2p + 32);
    float4 w2b_n  = *(const float4*)(wh2p + 36);

    // compute P(0) -> Ps[0]
    {
        float* pd = &Ps[0][mrow*PSTR + kq];
        float pa[4], pb[4];
#pragma unroll
        for (int tt = 0; tt < 4; tt++) {
            float e0 = w1 + ((const float*)&w2a)[tt]; e0 = (e0>=0.f)?e0:0.2f*e0;
            float e1 = w1 + ((const float*)&w2b)[tt]; e1 = (e1>=0.f)?e1:0.2f*e1;
            pa[tt] = ((mw >> (kq+tt))   & 1u) ? to_tf32(__expf(e0)*iz) : 0.f;
            pb[tt] = ((mw >> (kq+tt+4)) & 1u) ? to_tf32(__expf(e1)*iz) : 0.f;
        }
        *(float4*)(pd)   = make_float4(pa[0], pb[0], pa[1], pb[1]);
        *(float4*)(pd+4) = make_float4(pa[2], pb[2], pa[3], pb[3]);
    }
    mw = mw_n; w2a = w2a_n; w2b = w2b_n;
    mw_n  = maskrow[2*(size_t)NN];
    w2a_n = *(const float4*)(wh2p + 64);
    w2b_n = *(const float4*)(wh2p + 68);

    for (int c = 0; c < NCH; c++) {
        CP_WAIT1();
        __syncthreads();

        // issue W(c+2) into slot (c+2)%3
        if (c + 2 < NCH) {
            uint32_t ds = wsBase + (uint32_t)((c+2)%3)*(128*PSTR*4);
            const float* gs = gWb + (size_t)wf*NN + (c+2)*32 + wp;
#pragma unroll
            for (int i = 0; i < 4; i++)
                cp_async16(ds + (wf*PSTR + wp + 4*i)*4, gs + 4*i);
        }
        CP_COMMIT();

        // compute P(c+1) -> Ps[(c+1)&1]; prefetch inputs for c+2
        if (c + 1 < NCH) {
            float* pd = &Ps[(c+1)&1][mrow*PSTR + kq];
            float pa[4], pb[4];
#pragma unroll
            for (int tt = 0; tt < 4; tt++) {
                float e0 = w1 + ((const float*)&w2a)[tt]; e0 = (e0>=0.f)?e0:0.2f*e0;
                float e1 = w1 + ((const float*)&w2b)[tt]; e1 = (e1>=0.f)?e1:0.2f*e1;
                pa[tt] = ((mw >> (kq+tt))   & 1u) ? to_tf32(__expf(e0)*iz) : 0.f;
                pb[tt] = ((mw >> (kq+tt+4)) & 1u) ? to_tf32(__expf(e1)*iz) : 0.f;
            }
            *(float4*)(pd)   = make_float4(pa[0], pb[0], pa[1], pb[1]);
            *(float4*)(pd+4) = make_float4(pa[2], pb[2], pa[3], pb[3]);
            mw = mw_n; w2a = w2a_n; w2b = w2b_n;
            if (c + 3 < NCH) {
                mw_n  = maskrow[(size_t)(c+3)*NN];
                w2a_n = *(const float4*)(wh2p + (c+3)*32);
                w2b_n = *(const float4*)(wh2p + (c+3)*32 + 4);
            }
        }

        // MMA(c)
        const float* ws = Ws[c % 3];
        const float* ps = Ps[c & 1];
#pragma unroll
        for (int ks = 0; ks < 4; ks++) {
            uint2 bf[4];
#pragma unroll
            for (int nf = 0; nf < 4; nf++)
                bf[nf] = *(const uint2*)&ws[(nband + nf*8 + g)*PSTR + ks*8 + 2*t];
#pragma unroll
            for (int mf = 0; mf < 2; mf++) {
                uint2 aLo = *(const uint2*)&ps[(mband + mf*16 + g    )*PSTR + ks*8 + 2*t];
                uint2 aHi = *(const uint2*)&ps[(mband + mf*16 + g + 8)*PSTR + ks*8 + 2*t];
#pragma unroll
                for (int nf = 0; nf < 4; nf++)
                    mma_tf32(acc[mf][nf], aLo.x, aHi.x, aLo.y, aHi.y, bf[nf].x, bf[nf].y);
            }
        }
        __syncthreads();
    }

    // epilogue: ELU + store
#pragma unroll
    for (int mf = 0; mf < 2; mf++) {
        int r0 = b*NN + n0 + mband + mf*16 + g;
#pragma unroll
        for (int nf = 0; nf < 4; nf++) {
            int col = nband + nf*8 + t*2;
            float d0 = acc[mf][nf][0], d1 = acc[mf][nf][1];
            float d2 = acc[mf][nf][2], d3 = acc[mf][nf][3];
            d0 = (d0 > 0.f) ? d0 : expm1f(d0);
            d1 = (d1 > 0.f) ? d1 : expm1f(d1);
            d2 = (d2 > 0.f) ? d2 : expm1f(d2);
            d3 = (d3 > 0.f) ? d3 : expm1f(d3);
            *(float2*)&out[(size_t)r0*FOUT + col]     = make_float2(d0, d1);
            *(float2*)&out[(size_t)(r0+8)*FOUT + col] = make_float2(d2, d3);
        }
    }
}

extern "C" void kernel_launch(void* const* d_in, const int* in_sizes, int n_in,
                              void* d_out, int out_size) {
    const float* h   = (const float*)d_in[0];
    const int*   adj = (const int*)  d_in[1];
    const float* W   = (const float*)d_in[2];
    const float* a   = (const float*)d_in[3];
    float* out = (float*)d_out;

    k_gemm  <<<ROWS/64, 256>>>(h, W, a);
    { dim3 g(NCH, NB); k_trans<<<g, 128>>>(); }
    k_stats <<<ROWS/8,  256>>>(adj);
    { dim3 g(NN/64, NB); k_pv<<<g, 256>>>(out); }
}

// round 12
// speedup vs baseline: 1.7084x; 1.7084x over previous
#include <cuda_runtime.h>
#include <cstdint>

#define NB 4
#define NN 4096
#define FIN 256
#define FOUT 128
#define ROWS (NB*NN)
#define NCH 128            // chunk32 count
#define NC64 64            // chunk64 count
#define PSTR2 72           // smem row stride (words) for 64-k tiles; 72%32=8 -> conflict-free LDS.64
#define TILEB (128*PSTR2*4)   // 36864 bytes per W tile
#define L2E 1.4426950408889634f

// -------- scratch (static __device__, no allocs) --------
__device__ float    g_Wh[(size_t)ROWS*FOUT];            // 8 MB  Wh row-major
__device__ float    g_WhB[(size_t)NB*FOUT*NN];          // 8 MB  [b][f][pos] tf32, pi-ordered, pair-permuted
__device__ float    g_Wh1[ROWS];
__device__ float    g_Wh2[ROWS];
__device__ float    g_Wh2p[NB*NN];                      // wh2[pi] * log2(e)
__device__ float    g_l2iZ[ROWS];                       // -log2(sum)
__device__ unsigned g_maskT[(size_t)NB*NCH*NN];         // [b][chunk32][n], bit l <-> m = pi(chunk,l)

// pi(c32, l) = (c32>>2)*128 + 4*l + (c32&3)

__device__ __forceinline__ float to_tf32(float x) {
    uint32_t b; asm("cvt.rna.tf32.f32 %0, %1;" : "=r"(b) : "f"(x));
    return __uint_as_float(b);
}
__device__ __forceinline__ float ex2f(float x) {
    float y; asm("ex2.approx.ftz.f32 %0, %1;" : "=f"(y) : "f"(x)); return y;
}
__device__ __forceinline__ float maskf(float p, unsigned m, int bit) {
    unsigned s = (unsigned)(((int)(m << (31 - bit))) >> 31);
    return __uint_as_float(__float_as_uint(p) & s);
}
__device__ __forceinline__ void mma_tf32(float* d, float a0, float a1, float a2, float a3,
                                         uint32_t b0, uint32_t b1) {
    asm volatile("mma.sync.aligned.m16n8k8.row.col.f32.tf32.tf32.f32 "
                 "{%0,%1,%2,%3}, {%4,%5,%6,%7}, {%8,%9}, {%0,%1,%2,%3};"
                 : "+f"(d[0]), "+f"(d[1]), "+f"(d[2]), "+f"(d[3])
                 : "r"(__float_as_uint(a0)), "r"(__float_as_uint(a1)),
                   "r"(__float_as_uint(a2)), "r"(__float_as_uint(a3)),
                   "r"(b0), "r"(b1));
}
__device__ __forceinline__ uint32_t smem_u32(const void* p) {
    uint32_t a;
    asm("{ .reg .u64 t; cvta.to.shared.u64 t, %1; cvt.u32.u64 %0, t; }" : "=r"(a) : "l"(p));
    return a;
}
__device__ __forceinline__ void bulk_g2s(uint32_t dst, const void* src, uint32_t bytes, uint32_t mbar) {
    asm volatile("cp.async.bulk.shared::cluster.global.mbarrier::complete_tx::bytes [%0], [%1], %2, [%3];"
                 :: "r"(dst), "l"(src), "r"(bytes), "r"(mbar) : "memory");
}
#define MBARRIER_INIT(addr, cnt) \
    asm volatile("mbarrier.init.shared.b64 [%0], %1;" :: "r"(addr), "r"(cnt) : "memory")
#define MBARRIER_EXPECT_TX(addr, tx) \
    asm volatile("mbarrier.arrive.expect_tx.shared.b64 _, [%0], %1;" :: "r"(addr), "r"(tx) : "memory")
#define MBARRIER_WAIT_PARITY(addr, par) do {                                   \
    uint32_t _m = (addr), _p = (par), _d;                                      \
    asm volatile("{\n\t.reg .pred p;\n\t"                                      \
        "mbarrier.try_wait.parity.acquire.cta.shared::cta.b64 p, [%1], %2;\n\t"\
        "selp.b32 %0, 1, 0, p;\n\t}" : "=r"(_d) : "r"(_m), "r"(_p) : "memory");\
    if (!_d) {                                                                 \
        asm volatile("{\n\t.reg .pred P1;\n\t"                                 \
        "W%=:\n\t"                                                             \
        "mbarrier.try_wait.parity.acquire.cta.shared::cta.b64 P1, [%0], %1, 0x989680;\n\t" \
        "@P1 bra.uni D%=;\n\t bra.uni W%=;\n\tD%=:\n\t}"                       \
        :: "r"(_m), "r"(_p) : "memory");                                       \
    } } while (0)

// ====== Kernel 1: Wh = h @ W (fp32 tiled GEMM) + fused Wh1/Wh2 rowvec ======
__global__ void __launch_bounds__(256) k_gemm(const float* __restrict__ h,
                                              const float* __restrict__ W,
                                              const float* __restrict__ a) {
    __shared__ float As[64][32];
    __shared__ float Bsm[32][FOUT];
    const int block_row = blockIdx.x * 64;
    const int tid = threadIdx.x;
    const int tx = tid & 31, ty = tid >> 5;
    const float4 a1v = ((const float4*)a)[tx];
    const float4 a2v = ((const float4*)a)[32 + tx];
    float acc[8][4];
#pragma unroll
    for (int r = 0; r < 8; r++) { acc[r][0]=acc[r][1]=acc[r][2]=acc[r][3]=0.f; }
    for (int k0 = 0; k0 < FIN; k0 += 32) {
#pragma unroll
        for (int i = tid; i < 64*32; i += 256) {
            int r = i >> 5, c = i & 31;
            As[r][c] = h[(size_t)(block_row + r)*FIN + k0 + c];
        }
#pragma unroll
        for (int i = tid; i < 32*FOUT; i += 256) {
            int r = i >> 7, c = i & 127;
            Bsm[r][c] = W[(size_t)(k0 + r)*FOUT + c];
        }
        __syncthreads();
#pragma unroll
        for (int kk = 0; kk < 32; kk++) {
            float4 bv = *(const float4*)&Bsm[kk][tx*4];
#pragma unroll
            for (int r = 0; r < 8; r++) {
                float av = As[ty*8 + r][kk];
                acc[r][0] += av*bv.x; acc[r][1] += av*bv.y;
                acc[r][2] += av*bv.z; acc[r][3] += av*bv.w;
            }
        }
        __syncthreads();
    }
#pragma unroll
    for (int r = 0; r < 8; r++) {
        *(float4*)&g_Wh[(size_t)(block_row + ty*8 + r)*FOUT + tx*4] =
            make_float4(acc[r][0], acc[r][1], acc[r][2], acc[r][3]);
        float s1 = acc[r][0]*a1v.x + acc[r][1]*a1v.y + acc[r][2]*a1v.z + acc[r][3]*a1v.w;
        float s2 = acc[r][0]*a2v.x + acc[r][1]*a2v.y + acc[r][2]*a2v.z + acc[r][3]*a2v.w;
#pragma unroll
        for (int off = 16; off; off >>= 1) {
            s1 += __shfl_xor_sync(0xffffffffu, s1, off);
            s2 += __shfl_xor_sync(0xffffffffu, s2, off);
        }
        if (tx == 0) {
            g_Wh1[block_row + ty*8 + r] = s1;
            g_Wh2[block_row + ty*8 + r] = s2;
        }
    }
}

// ==== Kernel 2: Wh -> WhB [b][f][pos] tf32 (pi order, pair-permute); Wh2p = wh2[pi]*L2E ====
__global__ void __launch_bounds__(128) k_trans() {
    __shared__ float ts[32*128];   // [l][f]
    const int cp = blockIdx.x, b = blockIdx.y, tid = threadIdx.x;
    const int mbase = (cp >> 2) << 7, moff = cp & 3;
#pragma unroll
    for (int i = 0; i < 8; i++) {
        int idx = tid + 128*i;
        int l = idx >> 5, f4 = idx & 31;
        int m = mbase + 4*l + moff;
        ((float4*)ts)[idx] = *(((const float4*)(g_Wh + (size_t)(b*NN + m)*FOUT)) + f4);
    }
    if (tid < 32)
        g_Wh2p[b*NN + cp*32 + tid] = L2E * g_Wh2[b*NN + mbase + 4*tid + moff];
    __syncthreads();
    const int f = tid;
    float* dst = g_WhB + ((size_t)b*FOUT + f)*NN + cp*32;
#pragma unroll
    for (int s = 0; s < 4; s++)
#pragma unroll
        for (int t = 0; t < 4; t++) {
            float2 v;
            v.x = to_tf32(ts[(s*8 + t    )*128 + f]);
            v.y = to_tf32(ts[(s*8 + t + 4)*128 + f]);
            *(float2*)(dst + s*8 + 2*t) = v;
        }
}

// ==== Kernel 3: one pass over adj (2x int4/iter): pack pi mask + store -log2(sum) ====
__global__ void __launch_bounds__(256) k_stats(const int* __restrict__ adj) {
    int warp = (blockIdx.x * blockDim.x + threadIdx.x) >> 5;
    int lane = threadIdx.x & 31;
    if (warp >= ROWS) return;
    const int row = warp, b = row >> 12, n = row & (NN-1);
    const float w1 = g_Wh1[row];
    const int4*   arow = (const int4*)(adj + (size_t)row * NN);
    const float4* w2   = (const float4*)(g_Wh2 + (size_t)b * NN);
    unsigned* mbase = g_maskT + (size_t)b*NCH*NN + n;
    float sum = 0.f;
#pragma unroll 2
    for (int gg = 0; gg < 16; gg++) {
        int4   av0 = arow[gg*64 + lane];
        int4   av1 = arow[gg*64 + 32 + lane];
        float4 ev0 = w2[gg*64 + lane];
        float4 ev1 = w2[gg*64 + 32 + lane];
        {
            float e0 = w1 + ev0.x; e0 = (e0>=0.f)?e0:0.2f*e0;
            float e1 = w1 + ev0.y; e1 = (e1>=0.f)?e1:0.2f*e1;
            float e2 = w1 + ev0.z; e2 = (e2>=0.f)?e2:0.2f*e2;
            float e3 = w1 + ev0.w; e3 = (e3>=0.f)?e3:0.2f*e3;
            unsigned b0 = __ballot_sync(0xffffffffu, av0.x > 0);
            unsigned b1 = __ballot_sync(0xffffffffu, av0.y > 0);
            unsigned b2 = __ballot_sync(0xffffffffu, av0.z > 0);
            unsigned b3 = __ballot_sync(0xffffffffu, av0.w > 0);
            if (av0.x > 0) sum += __expf(e0);
            if (av0.y > 0) sum += __expf(e1);
            if (av0.z > 0) sum += __expf(e2);
            if (av0.w > 0) sum += __expf(e3);
            if (lane < 4) {
                unsigned bb = (lane == 0) ? b0 : (lane == 1) ? b1 : (lane == 2) ? b2 : b3;
                mbase[(size_t)(gg*8 + lane) * NN] = bb;
            }
        }
        {
            float e0 = w1 + ev1.x; e0 = (e0>=0.f)?e0:0.2f*e0;
            float e1 = w1 + ev1.y; e1 = (e1>=0.f)?e1:0.2f*e1;
            float e2 = w1 + ev1.z; e2 = (e2>=0.f)?e2:0.2f*e2;
            float e3 = w1 + ev1.w; e3 = (e3>=0.f)?e3:0.2f*e3;
            unsigned b0 = __ballot_sync(0xffffffffu, av1.x > 0);
            unsigned b1 = __ballot_sync(0xffffffffu, av1.y > 0);
            unsigned b2 = __ballot_sync(0xffffffffu, av1.z > 0);
            unsigned b3 = __ballot_sync(0xffffffffu, av1.w > 0);
            if (av1.x > 0) sum += __expf(e0);
            if (av1.y > 0) sum += __expf(e1);
            if (av1.z > 0) sum += __expf(e2);
            if (av1.w > 0) sum += __expf(e3);
            if (lane < 4) {
                unsigned bb = (lane == 0) ? b0 : (lane == 1) ? b1 : (lane == 2) ? b2 : b3;
                mbase[(size_t)(gg*8 + 4 + lane) * NN] = bb;
            }
        }
    }
#pragma unroll
    for (int off = 16; off; off >>= 1) sum += __shfl_xor_sync(0xffffffffu, sum, off);
    if (lane == 0) g_l2iZ[row] = -__log2f(sum);
}

// ============ Kernel 4: PV via mma.sync tf32; register-direct P; bulk-async W ============
// 256 thr, 8 warps (4M x 2N), M tile 128, K chunk 64, 4-slot W ring, 1 barrier/chunk.
__global__ void __launch_bounds__(256) k_pv(float* __restrict__ out) {
    __shared__ __align__(16) float Ws[4][128*PSTR2];     // 147,456 B
    __shared__ __align__(8)  unsigned long long s_mbar[4];

    const int b   = blockIdx.y;
    const int n0  = blockIdx.x * 128;
    const int tid = threadIdx.x;
    const int warp = tid >> 5, lane = tid & 31;
    const int g = lane >> 2, t = lane & 3;
    const int mband = (warp >> 1) * 32;      // 4 M bands
    const int nband = (warp & 1) * 64;       // 2 N bands

    const uint32_t mb0 = smem_u32(&s_mbar[0]);
    const uint32_t wsBase = smem_u32(&Ws[0][0]);
    const float* gWb = g_WhB + (size_t)b*FOUT*NN;

    // per-row exp constants: rows mband + g + 8j, j=0..3  (mf = j>>1)
    float c1[4], c2[4];
#pragma unroll
    for (int j = 0; j < 4; j++) {
        int row = b*NN + n0 + mband + g + 8*j;
        float w1L = g_Wh1[row] * L2E;
        float l2  = g_l2iZ[row];
        c1[j] = w1L + l2;
        c2[j] = 0.2f*w1L + l2;
    }
    const unsigned* mrow0 = g_maskT + (size_t)b*NCH*NN + n0 + mband + g;
    const float*    w2b   = g_Wh2p + b*NN;

    float acc[2][8][4];
#pragma unroll
    for (int mf = 0; mf < 2; mf++)
#pragma unroll
        for (int nf = 0; nf < 8; nf++)
#pragma unroll
            for (int i = 0; i < 4; i++) acc[mf][nf][i] = 0.f;

    if (tid == 0) {
#pragma unroll
        for (int s = 0; s < 4; s++) MBARRIER_INIT(mb0 + 8*s, 1);
    }
    __syncthreads();

    // fill chunk cc into slot cc&3: tid0 expect_tx, warp leaders copy 16 rows each
#define FILL_CHUNK(cc) do {                                                    \
    uint32_t _mb = mb0 + 8*((cc) & 3);                                         \
    if (tid == 0) MBARRIER_EXPECT_TX(_mb, 128*256);                            \
    if (lane == 0) {                                                           \
        const float* _src = gWb + (size_t)(16*warp)*NN + (cc)*64;              \
        uint32_t _dst = wsBase + ((cc) & 3)*TILEB + (16*warp)*(PSTR2*4);       \
        _Pragma("unroll")                                                      \
        for (int _r = 0; _r < 16; _r++)                                        \
            bulk_g2s(_dst + _r*(PSTR2*4), _src + (size_t)_r*NN, 256, _mb);     \
    } } while (0)

    FILL_CHUNK(0); FILL_CHUNK(1); FILL_CHUNK(2);

    for (int c = 0; c < NC64; c++) {
        MBARRIER_WAIT_PARITY(mb0 + 8*(c & 3), (c >> 2) & 1);
        __syncthreads();                       // all warps done with slot (c-1)&3
        if (c + 3 < NC64) FILL_CHUNK(c + 3);

        // masks for this 64-chunk (two chunk32 rows)
        unsigned m0[4], m1[4];
        {
            const unsigned* mr = mrow0 + (size_t)(2*c)*NN;
#pragma unroll
            for (int j = 0; j < 4; j++) { m0[j] = mr[8*j]; m1[j] = mr[NN + 8*j]; }
        }
        const float* ws = Ws[c & 3];
        const float* w2c = w2b + c*64;

#pragma unroll
        for (int ks = 0; ks < 8; ks++) {
            const int lA = (ks & 3)*8 + t;           // chunk32-local logical index
            const int lB = lA + 4;
            const float w2A = w2c[(ks >> 2)*32 + lA];
            const float w2B = w2c[(ks >> 2)*32 + lB];
            // B fragments
            uint2 bf[8];
#pragma unroll
            for (int nf = 0; nf < 8; nf++)
                bf[nf] = *(const uint2*)&ws[(nband + nf*8 + g)*PSTR2 + ks*8 + 2*t];
#pragma unroll
            for (int mf = 0; mf < 2; mf++) {
                const unsigned mmA0 = (ks < 4) ? m0[2*mf]   : m1[2*mf];
                const unsigned mmA1 = (ks < 4) ? m0[2*mf+1] : m1[2*mf+1];
                float a0 = maskf(ex2f(fmaxf(w2A + c1[2*mf],   0.2f*w2A + c2[2*mf])),   mmA0, lA);
                float a1 = maskf(ex2f(fmaxf(w2A + c1[2*mf+1], 0.2f*w2A + c2[2*mf+1])), mmA1, lA);
                float a2 = maskf(ex2f(fmaxf(w2B + c1[2*mf],   0.2f*w2B + c2[2*mf])),   mmA0, lB);
                float a3 = maskf(ex2f(fmaxf(w2B + c1[2*mf+1], 0.2f*w2B + c2[2*mf+1])), mmA1, lB);
#pragma unroll
                for (int nf = 0; nf < 8; nf++)
                    mma_tf32(acc[mf][nf], a0, a1, a2, a3, bf[nf].x, bf[nf].y);
            }
        }
    }

    // epilogue: ELU + store
#pragma unroll
    for (int mf = 0; mf < 2; mf++) {
        int r0 = b*NN + n0 + mband + mf*16 + g;
#pragma unroll
        for (int nf = 0; nf < 8; nf++) {
            int col = nband + nf*8 + t*2;
            float d0 = acc[mf][nf][0], d1 = acc[mf][nf][1];
            float d2 = acc[mf][nf][2], d3 = acc[mf][nf][3];
            d0 = (d0 > 0.f) ? d0 : expm1f(d0);
            d1 = (d1 > 0.f) ? d1 : expm1f(d1);
            d2 = (d2 > 0.f) ? d2 : expm1f(d2);
            d3 = (d3 > 0.f) ? d3 : expm1f(d3);
            *(float2*)&out[(size_t)r0*FOUT + col]     = make_float2(d0, d1);
            *(float2*)&out[(size_t)(r0+8)*FOUT + col] = make_float2(d2, d3);
        }
    }
}

extern "C" void kernel_launch(void* const* d_in, const int* in_sizes, int n_in,
                              void* d_out, int out_size) {
    const float* h   = (const float*)d_in[0];
    const int*   adj = (const int*)  d_in[1];
    const float* W   = (const float*)d_in[2];
    const float* a   = (const float*)d_in[3];
    float* out = (float*)d_out;

    k_gemm  <<<ROWS/64, 256>>>(h, W, a);
    { dim3 g(NCH, NB); k_trans<<<g, 128>>>(); }
    k_stats <<<ROWS/8,  256>>>(adj);
    { dim3 g(NN/128, NB); k_pv<<<g, 256>>>(out); }
}

// round 15
// speedup vs baseline: 1.8063x; 1.0573x over previous
#include <cuda_runtime.h>
#include <cstdint>

#define NB 4
#define NN 4096
#define FIN 256
#define FOUT 128
#define ROWS (NB*NN)
#define NCH 128            // chunk32 count
#define NC64 64            // chunk64 count
#define PSTR2 72           // smem row stride (words); 72%32=8 -> conflict-free LDS.64
#define TILEB (128*PSTR2*4)   // 36864 bytes per W tile
#define L2E 1.4426950408889634f

// -------- scratch (static __device__, no allocs) --------
__device__ float    g_Wh[(size_t)ROWS*FOUT];            // 8 MB  Wh row-major
__device__ float    g_WhB[(size_t)NB*FOUT*NN];          // 8 MB  [b][f][pos] tf32, pi-ordered, pair-permuted
__device__ float    g_Wh1[ROWS];
__device__ float    g_Wh2[ROWS];
__device__ float    g_Wh2p[NB*NN];                      // wh2[pi] * log2(e)
__device__ float    g_l2iZ[ROWS];                       // -log2(sum)
__device__ unsigned g_maskT[(size_t)NB*NCH*NN];         // [b][chunk32][n], bit l <-> m = pi(chunk,l)

// pi(c32, l) = (c32>>2)*128 + 4*l + (c32&3)

__device__ __forceinline__ float to_tf32(float x) {
    uint32_t b; asm("cvt.rna.tf32.f32 %0, %1;" : "=r"(b) : "f"(x));
    return __uint_as_float(b);
}
__device__ __forceinline__ float ex2f(float x) {
    float y; asm("ex2.approx.ftz.f32 %0, %1;" : "=f"(y) : "f"(x)); return y;
}
__device__ __forceinline__ float maskf(float p, unsigned m, int bit) {
    unsigned s = (unsigned)(((int)(m << (31 - bit))) >> 31);
    return __uint_as_float(__float_as_uint(p) & s);
}
__device__ __forceinline__ void mma_tf32(float* d, float a0, float a1, float a2, float a3,
                                         uint32_t b0, uint32_t b1) {
    asm volatile("mma.sync.aligned.m16n8k8.row.col.f32.tf32.tf32.f32 "
                 "{%0,%1,%2,%3}, {%4,%5,%6,%7}, {%8,%9}, {%0,%1,%2,%3};"
                 : "+f"(d[0]), "+f"(d[1]), "+f"(d[2]), "+f"(d[3])
                 : "r"(__float_as_uint(a0)), "r"(__float_as_uint(a1)),
                   "r"(__float_as_uint(a2)), "r"(__float_as_uint(a3)),
                   "r"(b0), "r"(b1));
}
__device__ __forceinline__ uint32_t smem_u32(const void* p) {
    uint32_t a;
    asm("{ .reg .u64 t; cvta.to.shared.u64 t, %1; cvt.u32.u64 %0, t; }" : "=r"(a) : "l"(p));
    return a;
}
__device__ __forceinline__ void bulk_g2s(uint32_t dst, const void* src, uint32_t bytes, uint32_t mbar) {
    asm volatile("cp.async.bulk.shared::cluster.global.mbarrier::complete_tx::bytes [%0], [%1], %2, [%3];"
                 :: "r"(dst), "l"(src), "r"(bytes), "r"(mbar) : "memory");
}
#define MBARRIER_INIT(addr, cnt) \
    asm volatile("mbarrier.init.shared.b64 [%0], %1;" :: "r"(addr), "r"(cnt) : "memory")
#define MBARRIER_EXPECT_TX(addr, tx) \
    asm volatile("mbarrier.arrive.expect_tx.shared.b64 _, [%0], %1;" :: "r"(addr), "r"(tx) : "memory")
#define MBARRIER_WAIT_PARITY(addr, par) do {                                   \
    uint32_t _m = (addr), _p = (par), _d;                                      \
    asm volatile("{\n\t.reg .pred p;\n\t"                                      \
        "mbarrier.try_wait.parity.acquire.cta.shared::cta.b64 p, [%1], %2;\n\t"\
        "selp.b32 %0, 1, 0, p;\n\t}" : "=r"(_d) : "r"(_m), "r"(_p) : "memory");\
    if (!_d) {                                                                 \
        asm volatile("{\n\t.reg .pred P1;\n\t"                                 \
        "W%=:\n\t"                                                             \
        "mbarrier.try_wait.parity.acquire.cta.shared::cta.b64 P1, [%0], %1, 0x989680;\n\t" \
        "@P1 bra.uni D%=;\n\t bra.uni W%=;\n\tD%=:\n\t}"                       \
        :: "r"(_m), "r"(_p) : "memory");                                       \
    } } while (0)

// ====== Kernel 1: Wh = h @ W (fp32 tiled GEMM) + fused Wh1/Wh2 rowvec ======
__global__ void __launch_bounds__(256) k_gemm(const float* __restrict__ h,
                                              const float* __restrict__ W,
                                              const float* __restrict__ a) {
    __shared__ float As[64][32];
    __shared__ float Bsm[32][FOUT];
    const int block_row = blockIdx.x * 64;
    const int tid = threadIdx.x;
    const int tx = tid & 31, ty = tid >> 5;
    const float4 a1v = ((const float4*)a)[tx];
    const float4 a2v = ((const float4*)a)[32 + tx];
    float acc[8][4];
#pragma unroll
    for (int r = 0; r < 8; r++) { acc[r][0]=acc[r][1]=acc[r][2]=acc[r][3]=0.f; }
    for (int k0 = 0; k0 < FIN; k0 += 32) {
#pragma unroll
        for (int i = tid; i < 64*32; i += 256) {
            int r = i >> 5, c = i & 31;
            As[r][c] = h[(size_t)(block_row + r)*FIN + k0 + c];
        }
#pragma unroll
        for (int i = tid; i < 32*FOUT; i += 256) {
            int r = i >> 7, c = i & 127;
            Bsm[r][c] = W[(size_t)(k0 + r)*FOUT + c];
        }
        __syncthreads();
#pragma unroll
        for (int kk = 0; kk < 32; kk++) {
            float4 bv = *(const float4*)&Bsm[kk][tx*4];
#pragma unroll
            for (int r = 0; r < 8; r++) {
                float av = As[ty*8 + r][kk];
                acc[r][0] += av*bv.x; acc[r][1] += av*bv.y;
                acc[r][2] += av*bv.z; acc[r][3] += av*bv.w;
            }
        }
        __syncthreads();
    }
#pragma unroll
    for (int r = 0; r < 8; r++) {
        *(float4*)&g_Wh[(size_t)(block_row + ty*8 + r)*FOUT + tx*4] =
            make_float4(acc[r][0], acc[r][1], acc[r][2], acc[r][3]);
        float s1 = acc[r][0]*a1v.x + acc[r][1]*a1v.y + acc[r][2]*a1v.z + acc[r][3]*a1v.w;
        float s2 = acc[r][0]*a2v.x + acc[r][1]*a2v.y + acc[r][2]*a2v.z + acc[r][3]*a2v.w;
#pragma unroll
        for (int off = 16; off; off >>= 1) {
            s1 += __shfl_xor_sync(0xffffffffu, s1, off);
            s2 += __shfl_xor_sync(0xffffffffu, s2, off);
        }
        if (tx == 0) {
            g_Wh1[block_row + ty*8 + r] = s1;
            g_Wh2[block_row + ty*8 + r] = s2;
        }
    }
}

// ==== Kernel 2: Wh -> WhB [b][f][pos] tf32 (pi order, pair-permute); Wh2p = wh2[pi]*L2E ====
__global__ void __launch_bounds__(128) k_trans() {
    __shared__ float ts[32*128];   // [l][f]
    const int cp = blockIdx.x, b = blockIdx.y, tid = threadIdx.x;
    const int mbase = (cp >> 2) << 7, moff = cp & 3;
#pragma unroll
    for (int i = 0; i < 8; i++) {
        int idx = tid + 128*i;
        int l = idx >> 5, f4 = idx & 31;
        int m = mbase + 4*l + moff;
        ((float4*)ts)[idx] = *(((const float4*)(g_Wh + (size_t)(b*NN + m)*FOUT)) + f4);
    }
    if (tid < 32)
        g_Wh2p[b*NN + cp*32 + tid] = L2E * g_Wh2[b*NN + mbase + 4*tid + moff];
    __syncthreads();
    const int f = tid;
    float* dst = g_WhB + ((size_t)b*FOUT + f)*NN + cp*32;
#pragma unroll
    for (int s = 0; s < 4; s++)
#pragma unroll
        for (int t = 0; t < 4; t++) {
            float2 v;
            v.x = to_tf32(ts[(s*8 + t    )*128 + f]);
            v.y = to_tf32(ts[(s*8 + t + 4)*128 + f]);
            *(float2*)(dst + s*8 + 2*t) = v;
        }
}

// ==== Kernel 3: one pass over adj (2x int4/iter): pack pi mask + store -log2(sum) ====
__global__ void __launch_bounds__(256) k_stats(const int* __restrict__ adj) {
    int warp = (blockIdx.x * blockDim.x + threadIdx.x) >> 5;
    int lane = threadIdx.x & 31;
    if (warp >= ROWS) return;
    const int row = warp, b = row >> 12, n = row & (NN-1);
    const float w1 = g_Wh1[row];
    const int4*   arow = (const int4*)(adj + (size_t)row * NN);
    const float4* w2   = (const float4*)(g_Wh2 + (size_t)b * NN);
    unsigned* mbase = g_maskT + (size_t)b*NCH*NN + n;
    float sum = 0.f;
#pragma unroll 2
    for (int gg = 0; gg < 16; gg++) {
        int4   av0 = arow[gg*64 + lane];
        int4   av1 = arow[gg*64 + 32 + lane];
        float4 ev0 = w2[gg*64 + lane];
        float4 ev1 = w2[gg*64 + 32 + lane];
        {
            float e0 = w1 + ev0.x; e0 = (e0>=0.f)?e0:0.2f*e0;
            float e1 = w1 + ev0.y; e1 = (e1>=0.f)?e1:0.2f*e1;
            float e2 = w1 + ev0.z; e2 = (e2>=0.f)?e2:0.2f*e2;
            float e3 = w1 + ev0.w; e3 = (e3>=0.f)?e3:0.2f*e3;
            unsigned b0 = __ballot_sync(0xffffffffu, av0.x > 0);
            unsigned b1 = __ballot_sync(0xffffffffu, av0.y > 0);
            unsigned b2 = __ballot_sync(0xffffffffu, av0.z > 0);
            unsigned b3 = __ballot_sync(0xffffffffu, av0.w > 0);
            if (av0.x > 0) sum += __expf(e0);
            if (av0.y > 0) sum += __expf(e1);
            if (av0.z > 0) sum += __expf(e2);
            if (av0.w > 0) sum += __expf(e3);
            if (lane < 4) {
                unsigned bb = (lane == 0) ? b0 : (lane == 1) ? b1 : (lane == 2) ? b2 : b3;
                mbase[(size_t)(gg*8 + lane) * NN] = bb;
            }
        }
        {
            float e0 = w1 + ev1.x; e0 = (e0>=0.f)?e0:0.2f*e0;
            float e1 = w1 + ev1.y; e1 = (e1>=0.f)?e1:0.2f*e1;
            float e2 = w1 + ev1.z; e2 = (e2>=0.f)?e2:0.2f*e2;
            float e3 = w1 + ev1.w; e3 = (e3>=0.f)?e3:0.2f*e3;
            unsigned b0 = __ballot_sync(0xffffffffu, av1.x > 0);
            unsigned b1 = __ballot_sync(0xffffffffu, av1.y > 0);
            unsigned b2 = __ballot_sync(0xffffffffu, av1.z > 0);
            unsigned b3 = __ballot_sync(0xffffffffu, av1.w > 0);
            if (av1.x > 0) sum += __expf(e0);
            if (av1.y > 0) sum += __expf(e1);
            if (av1.z > 0) sum += __expf(e2);
            if (av1.w > 0) sum += __expf(e3);
            if (lane < 4) {
                unsigned bb = (lane == 0) ? b0 : (lane == 1) ? b1 : (lane == 2) ? b2 : b3;
                mbase[(size_t)(gg*8 + 4 + lane) * NN] = bb;
            }
        }
    }
#pragma unroll
    for (int off = 16; off; off >>= 1) sum += __shfl_xor_sync(0xffffffffu, sum, off);
    if (lane == 0) g_l2iZ[row] = -__log2f(sum);
}

// ============ Kernel 4: PV via mma.sync tf32; register-direct P; bulk-async W ============
// 512 thr, 16 warps (8M x 2N), warp tile 16x64. M tile 128, K chunk 64,
// 4-slot W ring, 1 barrier/chunk. 4 warps/SMSP for latency hiding.
__global__ void __launch_bounds__(512) k_pv(float* __restrict__ out) {
    __shared__ __align__(16) float Ws[4][128*PSTR2];     // 147,456 B
    __shared__ __align__(8)  unsigned long long s_mbar[4];

    const int b   = blockIdx.y;
    const int n0  = blockIdx.x * 128;
    const int tid = threadIdx.x;
    const int warp = tid >> 5, lane = tid & 31;
    const int g = lane >> 2, t = lane & 3;
    const int mband = (warp >> 1) * 16;      // 8 M bands of 16
    const int nband = (warp & 1) * 64;       // 2 N bands of 64

    const uint32_t mb0 = smem_u32(&s_mbar[0]);
    const uint32_t wsBase = smem_u32(&Ws[0][0]);
    const float* gWb = g_WhB + (size_t)b*FOUT*NN;

    // per-row exp constants: rows mband + g + 8j, j=0..1
    float c1[2], c2[2];
#pragma unroll
    for (int j = 0; j < 2; j++) {
        int row = b*NN + n0 + mband + g + 8*j;
        float w1L = g_Wh1[row] * L2E;
        float l2  = g_l2iZ[row];
        c1[j] = w1L + l2;
        c2[j] = 0.2f*w1L + l2;
    }
    const unsigned* mrow0 = g_maskT + (size_t)b*NCH*NN + n0 + mband + g;
    const float*    w2b   = g_Wh2p + b*NN;

    float acc[8][4];
#pragma unroll
    for (int nf = 0; nf < 8; nf++)
#pragma unroll
        for (int i = 0; i < 4; i++) acc[nf][i] = 0.f;

    if (tid == 0) {
#pragma unroll
        for (int s = 0; s < 4; s++) MBARRIER_INIT(mb0 + 8*s, 1);
    }
    __syncthreads();

    // fill chunk cc into slot cc&3: tid0 expect_tx, 16 warp leaders copy 8 rows each
#define FILL_CHUNK(cc) do {                                                    \
    uint32_t _mb = mb0 + 8*((cc) & 3);                                         \
    if (tid == 0) MBARRIER_EXPECT_TX(_mb, 128*256);                            \
    if (lane == 0) {                                                           \
        const float* _src = gWb + (size_t)(8*warp)*NN + (cc)*64;               \
        uint32_t _dst = wsBase + ((cc) & 3)*TILEB + (8*warp)*(PSTR2*4);        \
        _Pragma("unroll")                                                      \
        for (int _r = 0; _r < 8; _r++)                                         \
            bulk_g2s(_dst + _r*(PSTR2*4), _src + (size_t)_r*NN, 256, _mb);     \
    } } while (0)

    FILL_CHUNK(0); FILL_CHUNK(1); FILL_CHUNK(2);

    for (int c = 0; c < NC64; c++) {
        MBARRIER_WAIT_PARITY(mb0 + 8*(c & 3), (c >> 2) & 1);
        __syncthreads();                       // all warps done with slot (c-1)&3
        if (c + 3 < NC64) FILL_CHUNK(c + 3);

        // masks for this 64-chunk (two chunk32 rows x two m-rows)
        unsigned m00, m01, m10, m11;
        {
            const unsigned* mr = mrow0 + (size_t)(2*c)*NN;
            m00 = mr[0]; m01 = mr[8];
            m10 = mr[NN]; m11 = mr[NN + 8];
        }
        const float* ws = Ws[c & 3];
        const float* w2c = w2b + c*64;

#pragma unroll
        for (int ks = 0; ks < 8; ks++) {
            const int lA = (ks & 3)*8 + t;           // chunk32-local logical index
            const int lB = lA + 4;
            const float w2A = w2c[(ks >> 2)*32 + lA];
            const float w2B = w2c[(ks >> 2)*32 + lB];
            const float w2A2 = 0.2f*w2A, w2B2 = 0.2f*w2B;
            const unsigned mA0 = (ks < 4) ? m00 : m10;
            const unsigned mA1 = (ks < 4) ? m01 : m11;
            // B fragments
            uint2 bf[8];
#pragma unroll
            for (int nf = 0; nf < 8; nf++)
                bf[nf] = *(const uint2*)&ws[(nband + nf*8 + g)*PSTR2 + ks*8 + 2*t];
            float a0 = maskf(ex2f(fmaxf(w2A + c1[0], w2A2 + c2[0])), mA0, lA);
            float a1 = maskf(ex2f(fmaxf(w2A + c1[1], w2A2 + c2[1])), mA1, lA);
            float a2 = maskf(ex2f(fmaxf(w2B + c1[0], w2B2 + c2[0])), mA0, lB);
            float a3 = maskf(ex2f(fmaxf(w2B + c1[1], w2B2 + c2[1])), mA1, lB);
#pragma unroll
            for (int nf = 0; nf < 8; nf++)
                mma_tf32(acc[nf], a0, a1, a2, a3, bf[nf].x, bf[nf].y);
        }
    }

    // epilogue: ELU + store (rows r0, r0+8)
    {
        int r0 = b*NN + n0 + mband + g;
#pragma unroll
        for (int nf = 0; nf < 8; nf++) {
            int col = nband + nf*8 + t*2;
            float d0 = acc[nf][0], d1 = acc[nf][1];
            float d2 = acc[nf][2], d3 = acc[nf][3];
            d0 = (d0 > 0.f) ? d0 : expm1f(d0);
            d1 = (d1 > 0.f) ? d1 : expm1f(d1);
            d2 = (d2 > 0.f) ? d2 : expm1f(d2);
            d3 = (d3 > 0.f) ? d3 : expm1f(d3);
            *(float2*)&out[(size_t)r0*FOUT + col]     = make_float2(d0, d1);
            *(float2*)&out[(size_t)(r0+8)*FOUT + col] = make_float2(d2, d3);
        }
    }
}

extern "C" void kernel_launch(void* const* d_in, const int* in_sizes, int n_in,
                              void* d_out, int out_size) {
    const float* h   = (const float*)d_in[0];
    const int*   adj = (const int*)  d_in[1];
    const float* W   = (const float*)d_in[2];
    const float* a   = (const float*)d_in[3];
    float* out = (float*)d_out;

    k_gemm  <<<ROWS/64, 256>>>(h, W, a);
    { dim3 g(NCH, NB); k_trans<<<g, 128>>>(); }
    k_stats <<<ROWS/8,  256>>>(adj);
    { dim3 g(NN/128, NB); k_pv<<<g, 512>>>(out); }
}